// round 9
// baseline (speedup 1.0000x reference)
#include <cuda_runtime.h>
#include <cuda_fp16.h>
#include <cstdint>

// ---------------- problem constants ----------------
#define D_MODEL   1024
#define NUM_HEADS 16
#define HEAD_DIM  64
#define BATCH     2
#define SEQ       2048
#define M_TOT     (BATCH * SEQ)      // 4096
#define QKV_N     (3 * D_MODEL)      // 3072

// scratch (no cudaMalloc allowed)
__device__ float g_qkv[(size_t)M_TOT * QKV_N];      // [B,S,3D]
__device__ float g_attn[(size_t)M_TOT * D_MODEL];   // [B,H,S,hd] == reshape(B,S,D)
__device__ float g_xr[(size_t)M_TOT * D_MODEL];     // tf32-rounded x
__device__ float g_wqkvr[(size_t)QKV_N * D_MODEL];  // tf32-rounded Wqkv
__device__ float g_wor[(size_t)D_MODEL * D_MODEL];  // tf32-rounded Wo

// ---------------- tf32 helpers ----------------
__device__ __forceinline__ uint32_t f2tf32(float f) {
    uint32_t u;
    asm("cvt.rna.tf32.f32 %0, %1;" : "=r"(u) : "f"(f));
    return u;
}
__device__ __forceinline__ float tf32r(float f) { return __uint_as_float(f2tf32(f)); }

__device__ __forceinline__ void mma_tf32(float c[4], uint32_t a0, uint32_t a1,
                                         uint32_t a2, uint32_t a3,
                                         uint32_t b0, uint32_t b1) {
    asm volatile(
        "mma.sync.aligned.m16n8k8.row.col.f32.tf32.tf32.f32 "
        "{%0,%1,%2,%3}, {%4,%5,%6,%7}, {%8,%9}, {%0,%1,%2,%3};\n"
        : "+f"(c[0]), "+f"(c[1]), "+f"(c[2]), "+f"(c[3])
        : "r"(a0), "r"(a1), "r"(a2), "r"(a3), "r"(b0), "r"(b1));
}

// ---------------- fp16 helpers (attention) ----------------
__device__ __forceinline__ void mma_f16(float c[4], uint32_t a0, uint32_t a1,
                                        uint32_t a2, uint32_t a3,
                                        uint32_t b0, uint32_t b1) {
    asm volatile(
        "mma.sync.aligned.m16n8k16.row.col.f32.f16.f16.f32 "
        "{%0,%1,%2,%3}, {%4,%5,%6,%7}, {%8,%9}, {%0,%1,%2,%3};\n"
        : "+f"(c[0]), "+f"(c[1]), "+f"(c[2]), "+f"(c[3])
        : "r"(a0), "r"(a1), "r"(a2), "r"(a3), "r"(b0), "r"(b1));
}
__device__ __forceinline__ uint32_t packh2(float lo, float hi) {
    uint32_t r;
    asm("cvt.rn.f16x2.f32 %0, %2, %1;" : "=r"(r) : "f"(lo), "f"(hi));
    return r;
}
__device__ __forceinline__ void ldsm_x4_t(uint32_t r[4], const __half* p) {
    uint32_t a = (uint32_t)__cvta_generic_to_shared(p);
    asm volatile("ldmatrix.sync.aligned.m8n8.x4.trans.shared.b16 {%0,%1,%2,%3}, [%4];"
                 : "=r"(r[0]), "=r"(r[1]), "=r"(r[2]), "=r"(r[3]) : "r"(a));
}

// ---------------- cp.async helpers ----------------
__device__ __forceinline__ void cp_async16(float* smem_dst, const float* gsrc) {
    uint32_t d = (uint32_t)__cvta_generic_to_shared(smem_dst);
    asm volatile("cp.async.ca.shared.global [%0], [%1], 16;" :: "r"(d), "l"(gsrc));
}
#define CP_COMMIT() asm volatile("cp.async.commit_group;")
#define CP_WAIT1()  asm volatile("cp.async.wait_group 1;" ::: "memory")

// ---------------- tf32 rounding pre-pass ----------------
__global__ void round_tf32_kernel(const float* __restrict__ in, float* __restrict__ out, int n4)
{
    int i = blockIdx.x * blockDim.x + threadIdx.x;
    if (i < n4) {
        float4 v = ((const float4*)in)[i];
        v.x = tf32r(v.x); v.y = tf32r(v.y); v.z = tf32r(v.z); v.w = tf32r(v.w);
        ((float4*)out)[i] = v;
    }
}

// ---------------- tf32 tensor-core GEMM, 3-stage cp.async pipeline ----------------
// C[M,N] = A[M,K] * Bw[N,K]^T + bias[N]; A, Bw already tf32-rounded.
// 128x128x32 tiles, 256 threads, warp tile 64x32 (4x4 m16n8k8).
#define BM 128
#define BN 128
#define BK 32
#define LDT 36
#define GST ((BM + BN) * LDT)        // floats per stage = 9216
#define GSM_TOT (3 * GST)            // 27648 floats = 110592 B

__global__ __launch_bounds__(256, 2)
void gemm_tf32(const float* __restrict__ A, const float* __restrict__ Bw,
               const float* __restrict__ bias, float* __restrict__ C,
               int N, int K)
{
    extern __shared__ float smg[];

    const int tid  = threadIdx.x;
    const int lane = tid & 31;
    const int wid  = tid >> 5;
    const int g = lane >> 2;
    const int t = lane & 3;
    const int wm = wid >> 2;
    const int wn = wid & 3;
    const int row0 = blockIdx.y * BM;
    const int col0 = blockIdx.x * BN;

    const int kg = tid & 7;       // float4 index along K
    const int lr = tid >> 3;      // row 0..31 (+i*32)
    const float* Ag = A  + (size_t)(row0 + lr) * K + kg * 4;
    const float* Bg = Bw + (size_t)(col0 + lr) * K + kg * 4;

    const int NP = K / BK;

    // issue cp.async copies for panel p into stage p%3
    auto issue = [&](int p) {
        float* As = smg + (p % 3) * GST;
        float* Bs = As + BM * LDT;
        const int kp = p * BK;
#pragma unroll
        for (int i = 0; i < 4; i++) {
            cp_async16(&As[(lr + i * 32) * LDT + kg * 4], Ag + (size_t)i * 32 * K + kp);
            cp_async16(&Bs[(lr + i * 32) * LDT + kg * 4], Bg + (size_t)i * 32 * K + kp);
        }
    };

    issue(0); CP_COMMIT();
    issue(1); CP_COMMIT();

    float c[4][4][4];
#pragma unroll
    for (int mt = 0; mt < 4; mt++)
#pragma unroll
        for (int nt = 0; nt < 4; nt++)
#pragma unroll
            for (int r = 0; r < 4; r++) c[mt][nt][r] = 0.f;

    for (int p = 0; p < NP; p++) {
        CP_WAIT1();          // panel p's group complete (this thread)
        __syncthreads();     // all threads' copies for panel p visible; stage (p-1)%3 free
        if (p + 2 < NP) issue(p + 2);
        CP_COMMIT();         // always commit (uniform group arithmetic)

        const float* As = smg + (p % 3) * GST;
        const float* Bs = As + BM * LDT;
        const float* Awp = &As[(wm * 64) * LDT];
        const float* Bwp = &Bs[(wn * 32) * LDT];
#pragma unroll
        for (int kq = 0; kq < BK; kq += 8) {
            uint32_t af[4][4], bf[4][2];
#pragma unroll
            for (int mt = 0; mt < 4; mt++) {
                const float* ap = Awp + (mt * 16 + g) * LDT + kq + t;
                af[mt][0] = __float_as_uint(ap[0]);
                af[mt][1] = __float_as_uint(ap[8 * LDT]);
                af[mt][2] = __float_as_uint(ap[4]);
                af[mt][3] = __float_as_uint(ap[8 * LDT + 4]);
            }
#pragma unroll
            for (int nt = 0; nt < 4; nt++) {
                const float* bp = Bwp + (nt * 8 + g) * LDT + kq + t;
                bf[nt][0] = __float_as_uint(bp[0]);
                bf[nt][1] = __float_as_uint(bp[4]);
            }
#pragma unroll
            for (int mt = 0; mt < 4; mt++)
#pragma unroll
                for (int nt = 0; nt < 4; nt++)
                    mma_tf32(c[mt][nt], af[mt][0], af[mt][1], af[mt][2], af[mt][3],
                             bf[nt][0], bf[nt][1]);
        }
    }

    // ---- epilogue: bias + store ----
#pragma unroll
    for (int mt = 0; mt < 4; mt++) {
        int row = row0 + wm * 64 + mt * 16 + g;
#pragma unroll
        for (int nt = 0; nt < 4; nt++) {
            int col = col0 + wn * 32 + nt * 8 + 2 * t;
            float b0 = bias[col], b1 = bias[col + 1];
            float2 v0 = make_float2(c[mt][nt][0] + b0, c[mt][nt][1] + b1);
            float2 v1 = make_float2(c[mt][nt][2] + b0, c[mt][nt][3] + b1);
            *(float2*)&C[(size_t)row * N + col] = v0;
            *(float2*)&C[(size_t)(row + 8) * N + col] = v1;
        }
    }
}

// ---------------- fp16-split tensor-core flash attention ----------------
// CTA: 128 queries x 64-key tiles, 8 warps (16 query rows each).
// QK^T: 3-term fp16 split (near-fp32). PV: P fp16, V 2-term split.
// Epilogue rounds outputs to tf32 (they feed GEMM2's A operand).
#define SH 72                       // smem row stride in halves (144 B)
#define OQH 0
#define OQL (128 * SH)
#define OKH (2 * 128 * SH)
#define OKL (OKH + 64 * SH)
#define OVH (OKL + 64 * SH)
#define OVL (OVH + 64 * SH)
#define OPS (OVL + 64 * SH)
#define SMH_TOT (OPS + 128 * SH)    // 46080 halves = 92160 B

__global__ __launch_bounds__(256, 2)
void attn_fp16(const float* __restrict__ qkv, float* __restrict__ attn_out)
{
    extern __shared__ __half smh[];

    const int tid  = threadIdx.x;
    const int lane = tid & 31;
    const int w = tid >> 5;
    const int g = lane >> 2;
    const int t = lane & 3;
    const int b = blockIdx.y >> 4, h = blockIdx.y & 15;
    const int qt = (int)gridDim.x - 1 - (int)blockIdx.x;   // heavy CTAs first
    const int q0 = qt * 128;
    const float* base = qkv + (size_t)b * SEQ * QKV_N + h * (3 * HEAD_DIM);
    const float SC = 0.125f * 1.4426950408889634f;   // 1/sqrt(hd) * log2(e)

    // ---- load Q tile, split into fp16 hi/lo ----
#pragma unroll
    for (int i = 0; i < 8; i++) {
        int idx = tid + i * 256;
        int r = idx >> 4, c4 = (idx & 15) << 2;
        float4 q = *(const float4*)(base + (size_t)(q0 + r) * QKV_N + c4);
        float f[4] = {q.x * SC, q.y * SC, q.z * SC, q.w * SC};
        float hh[4], ll[4];
#pragma unroll
        for (int e = 0; e < 4; e++) {
            hh[e] = __half2float(__float2half_rn(f[e]));
            ll[e] = f[e] - hh[e];
        }
        uint32_t* ph = (uint32_t*)&smh[OQH + r * SH + c4];
        uint32_t* pl = (uint32_t*)&smh[OQL + r * SH + c4];
        ph[0] = packh2(hh[0], hh[1]); ph[1] = packh2(hh[2], hh[3]);
        pl[0] = packh2(ll[0], ll[1]); pl[1] = packh2(ll[2], ll[3]);
    }

    float o[8][4];
#pragma unroll
    for (int nt = 0; nt < 8; nt++)
#pragma unroll
        for (int r = 0; r < 4; r++) o[nt][r] = 0.f;
    float m0 = -1e30f, m1 = -1e30f, l0 = 0.f, l1 = 0.f;

    const int wr = w * 16;
    const int myrow = q0 + wr;
    const int rowg0 = myrow + g, rowg1 = myrow + g + 8;
    const int nkt = qt * 2 + 2;

    // ldmatrix per-thread source row/col selectors
    const int lr7  = lane & 7;
    const int ksel = (lane >> 3) & 1;
    const int nsel = lane >> 4;

    for (int j = 0; j < nkt; j++) {
        const int k0 = j * 64;
        // register prefetch of K/V tile
        float4 kk[4], vv[4];
#pragma unroll
        for (int i = 0; i < 4; i++) {
            int idx = tid + i * 256;
            int r = idx >> 4, c4 = (idx & 15) << 2;
            const float* rp = base + (size_t)(k0 + r) * QKV_N + c4;
            kk[i] = *(const float4*)(rp + HEAD_DIM);
            vv[i] = *(const float4*)(rp + 2 * HEAD_DIM);
        }
        __syncthreads();   // previous tile fully consumed
#pragma unroll
        for (int i = 0; i < 4; i++) {
            int idx = tid + i * 256;
            int r = idx >> 4, c4 = (idx & 15) << 2;
            float kf[4] = {kk[i].x, kk[i].y, kk[i].z, kk[i].w};
            float vf[4] = {vv[i].x, vv[i].y, vv[i].z, vv[i].w};
            float kh[4], kl[4], vh[4], vl[4];
#pragma unroll
            for (int e = 0; e < 4; e++) {
                kh[e] = __half2float(__float2half_rn(kf[e])); kl[e] = kf[e] - kh[e];
                vh[e] = __half2float(__float2half_rn(vf[e])); vl[e] = vf[e] - vh[e];
            }
            uint32_t* p;
            p = (uint32_t*)&smh[OKH + r * SH + c4];
            p[0] = packh2(kh[0], kh[1]); p[1] = packh2(kh[2], kh[3]);
            p = (uint32_t*)&smh[OKL + r * SH + c4];
            p[0] = packh2(kl[0], kl[1]); p[1] = packh2(kl[2], kl[3]);
            p = (uint32_t*)&smh[OVH + r * SH + c4];
            p[0] = packh2(vh[0], vh[1]); p[1] = packh2(vh[2], vh[3]);
            p = (uint32_t*)&smh[OVL + r * SH + c4];
            p[0] = packh2(vl[0], vl[1]); p[1] = packh2(vl[2], vl[3]);
        }
        __syncthreads();

        if (k0 <= myrow + 15) {   // not fully masked for this warp
            // ---- S = Q K^T  (3-term fp16 split) ----
            float s[8][4];
#pragma unroll
            for (int nt = 0; nt < 8; nt++)
#pragma unroll
                for (int r = 0; r < 4; r++) s[nt][r] = 0.f;

#pragma unroll
            for (int kq = 0; kq < 4; kq++) {
                const int kc = kq * 16;
                const int a_lo = (wr + g) * SH + kc + 2 * t;
                const int a_hi = (wr + g + 8) * SH + kc + 2 * t;
                uint32_t ah0 = *(uint32_t*)&smh[OQH + a_lo];
                uint32_t ah1 = *(uint32_t*)&smh[OQH + a_hi];
                uint32_t ah2 = *(uint32_t*)&smh[OQH + a_lo + 8];
                uint32_t ah3 = *(uint32_t*)&smh[OQH + a_hi + 8];
                uint32_t al0 = *(uint32_t*)&smh[OQL + a_lo];
                uint32_t al1 = *(uint32_t*)&smh[OQL + a_hi];
                uint32_t al2 = *(uint32_t*)&smh[OQL + a_lo + 8];
                uint32_t al3 = *(uint32_t*)&smh[OQL + a_hi + 8];
#pragma unroll
                for (int nt = 0; nt < 8; nt++) {
                    const int bidx = (nt * 8 + g) * SH + kc + 2 * t;
                    uint32_t bh0 = *(uint32_t*)&smh[OKH + bidx];
                    uint32_t bh1 = *(uint32_t*)&smh[OKH + bidx + 8];
                    uint32_t bl0 = *(uint32_t*)&smh[OKL + bidx];
                    uint32_t bl1 = *(uint32_t*)&smh[OKL + bidx + 8];
                    mma_f16(s[nt], ah0, ah1, ah2, ah3, bh0, bh1);
                    mma_f16(s[nt], al0, al1, al2, al3, bh0, bh1);
                    mma_f16(s[nt], ah0, ah1, ah2, ah3, bl0, bl1);
                }
            }

            // ---- causal mask (diagonal-straddling tiles only) ----
            if (k0 + 63 > myrow) {
#pragma unroll
                for (int nt = 0; nt < 8; nt++) {
                    int c = k0 + nt * 8 + 2 * t;
                    if (c > rowg0)     s[nt][0] = -1e30f;
                    if (c + 1 > rowg0) s[nt][1] = -1e30f;
                    if (c > rowg1)     s[nt][2] = -1e30f;
                    if (c + 1 > rowg1) s[nt][3] = -1e30f;
                }
            }

            // ---- online softmax (exp2 domain), P -> fp16 smem ----
            float rm0 = -1e30f, rm1 = -1e30f;
#pragma unroll
            for (int nt = 0; nt < 8; nt++) {
                rm0 = fmaxf(rm0, fmaxf(s[nt][0], s[nt][1]));
                rm1 = fmaxf(rm1, fmaxf(s[nt][2], s[nt][3]));
            }
            rm0 = fmaxf(rm0, __shfl_xor_sync(0xffffffffu, rm0, 1));
            rm0 = fmaxf(rm0, __shfl_xor_sync(0xffffffffu, rm0, 2));
            rm1 = fmaxf(rm1, __shfl_xor_sync(0xffffffffu, rm1, 1));
            rm1 = fmaxf(rm1, __shfl_xor_sync(0xffffffffu, rm1, 2));
            float mn0 = fmaxf(m0, rm0), mn1 = fmaxf(m1, rm1);
            float alp0 = exp2f(m0 - mn0), alp1 = exp2f(m1 - mn1);
            float rs0 = 0.f, rs1 = 0.f;
#pragma unroll
            for (int nt = 0; nt < 8; nt++) {
                s[nt][0] = exp2f(s[nt][0] - mn0);
                s[nt][1] = exp2f(s[nt][1] - mn0);
                s[nt][2] = exp2f(s[nt][2] - mn1);
                s[nt][3] = exp2f(s[nt][3] - mn1);
                rs0 += s[nt][0] + s[nt][1];
                rs1 += s[nt][2] + s[nt][3];
                *(uint32_t*)&smh[OPS + (wr + g) * SH + nt * 8 + 2 * t] =
                    packh2(s[nt][0], s[nt][1]);
                *(uint32_t*)&smh[OPS + (wr + g + 8) * SH + nt * 8 + 2 * t] =
                    packh2(s[nt][2], s[nt][3]);
            }
            rs0 += __shfl_xor_sync(0xffffffffu, rs0, 1);
            rs0 += __shfl_xor_sync(0xffffffffu, rs0, 2);
            rs1 += __shfl_xor_sync(0xffffffffu, rs1, 1);
            rs1 += __shfl_xor_sync(0xffffffffu, rs1, 2);
            l0 = l0 * alp0 + rs0;  l1 = l1 * alp1 + rs1;
            m0 = mn0;  m1 = mn1;
#pragma unroll
            for (int nt = 0; nt < 8; nt++) {
                o[nt][0] *= alp0; o[nt][1] *= alp0;
                o[nt][2] *= alp1; o[nt][3] *= alp1;
            }
            __syncwarp();   // P stores visible to warp

            // ---- O += P V  (P fp16, V 2-term split; V^T via ldmatrix.trans) ----
#pragma unroll
            for (int kq = 0; kq < 4; kq++) {
                const int kc = kq * 16;
                const int a_lo = (wr + g) * SH + kc + 2 * t;
                const int a_hi = (wr + g + 8) * SH + kc + 2 * t;
                uint32_t pa0 = *(uint32_t*)&smh[OPS + a_lo];
                uint32_t pa1 = *(uint32_t*)&smh[OPS + a_hi];
                uint32_t pa2 = *(uint32_t*)&smh[OPS + a_lo + 8];
                uint32_t pa3 = *(uint32_t*)&smh[OPS + a_hi + 8];
                const int vrow = (kc + lr7 + 8 * ksel) * SH + nsel * 8;
#pragma unroll
                for (int np = 0; np < 4; np++) {
                    uint32_t bh[4], bl[4];
                    ldsm_x4_t(bh, &smh[OVH + vrow + np * 16]);
                    ldsm_x4_t(bl, &smh[OVL + vrow + np * 16]);
                    mma_f16(o[np * 2],     pa0, pa1, pa2, pa3, bh[0], bh[1]);
                    mma_f16(o[np * 2],     pa0, pa1, pa2, pa3, bl[0], bl[1]);
                    mma_f16(o[np * 2 + 1], pa0, pa1, pa2, pa3, bh[2], bh[3]);
                    mma_f16(o[np * 2 + 1], pa0, pa1, pa2, pa3, bl[2], bl[3]);
                }
            }
            __syncwarp();
        }
    }

    // ---- normalize + tf32-round + write [B,H,S,hd] (feeds GEMM2's A) ----
    float inv0 = 1.0f / l0, inv1 = 1.0f / l1;
    float* op = attn_out + ((size_t)b * NUM_HEADS + h) * SEQ * HEAD_DIM;
#pragma unroll
    for (int nt = 0; nt < 8; nt++) {
        int c = nt * 8 + 2 * t;
        *(float2*)&op[(size_t)rowg0 * HEAD_DIM + c] =
            make_float2(tf32r(o[nt][0] * inv0), tf32r(o[nt][1] * inv0));
        *(float2*)&op[(size_t)rowg1 * HEAD_DIM + c] =
            make_float2(tf32r(o[nt][2] * inv1), tf32r(o[nt][3] * inv1));
    }
}

// ---------------- launch ----------------
extern "C" void kernel_launch(void* const* d_in, const int* in_sizes, int n_in,
                              void* d_out, int out_size)
{
    const float* x    = (const float*)d_in[0];
    const float* Wqkv = (const float*)d_in[1];
    const float* bqkv = (const float*)d_in[2];
    const float* Wo   = (const float*)d_in[3];
    const float* bo   = (const float*)d_in[4];
    float* out = (float*)d_out;

    float *qkv_ptr, *attn_ptr, *xr_ptr, *wqkvr_ptr, *wor_ptr;
    cudaGetSymbolAddress((void**)&qkv_ptr, g_qkv);
    cudaGetSymbolAddress((void**)&attn_ptr, g_attn);
    cudaGetSymbolAddress((void**)&xr_ptr, g_xr);
    cudaGetSymbolAddress((void**)&wqkvr_ptr, g_wqkvr);
    cudaGetSymbolAddress((void**)&wor_ptr, g_wor);

    const int gemm_smem = GSM_TOT * (int)sizeof(float);    // 110592 B
    const int attn_smem = SMH_TOT * (int)sizeof(__half);   // 92160 B
    cudaFuncSetAttribute(gemm_tf32, cudaFuncAttributeMaxDynamicSharedMemorySize, gemm_smem);
    cudaFuncSetAttribute(attn_fp16, cudaFuncAttributeMaxDynamicSharedMemorySize, attn_smem);

    // 0) pre-round GEMM operands to tf32 (numerically == cvt at staging)
    {
        int n4;
        n4 = (M_TOT * D_MODEL) / 4;
        round_tf32_kernel<<<(n4 + 255) / 256, 256>>>(x, xr_ptr, n4);
        n4 = (QKV_N * D_MODEL) / 4;
        round_tf32_kernel<<<(n4 + 255) / 256, 256>>>(Wqkv, wqkvr_ptr, n4);
        n4 = (D_MODEL * D_MODEL) / 4;
        round_tf32_kernel<<<(n4 + 255) / 256, 256>>>(Wo, wor_ptr, n4);
    }

    // 1) qkv = x @ Wqkv^T + bqkv   (tf32 tensor cores, 3-stage cp.async)
    gemm_tf32<<<dim3(QKV_N / BN, M_TOT / BM), 256, gemm_smem>>>(xr_ptr, wqkvr_ptr, bqkv, qkv_ptr, QKV_N, D_MODEL);
    // 2) causal flash attention (fp16-split tensor cores; output tf32-rounded)
    attn_fp16<<<dim3(SEQ / 128, BATCH * NUM_HEADS), 256, attn_smem>>>(qkv_ptr, attn_ptr);
    // 3) out = attn @ Wo^T + bo    (tf32 tensor cores, 3-stage cp.async)
    gemm_tf32<<<dim3(D_MODEL / BN, M_TOT / BM), 256, gemm_smem>>>(attn_ptr, wor_ptr, bo, out, D_MODEL, D_MODEL);
}

// round 13
// speedup vs baseline: 1.5908x; 1.5908x over previous
#include <cuda_runtime.h>
#include <cuda_fp16.h>
#include <cstdint>

// ---------------- problem constants ----------------
#define D_MODEL   1024
#define NUM_HEADS 16
#define HEAD_DIM  64
#define BATCH     2
#define SEQ       2048
#define M_TOT     (BATCH * SEQ)      // 4096
#define QKV_N     (3 * D_MODEL)      // 3072

// scratch (no cudaMalloc allowed)
__device__ float g_qkv[(size_t)M_TOT * QKV_N];      // [B,S,3D]
__device__ float g_attn[(size_t)M_TOT * D_MODEL];   // [B,H,S,hd] == reshape(B,S,D)

// ---------------- tf32 helpers (GEMM) ----------------
__device__ __forceinline__ uint32_t f2tf32(float f) {
    uint32_t u;
    asm("cvt.rna.tf32.f32 %0, %1;" : "=r"(u) : "f"(f));
    return u;
}
__device__ __forceinline__ void mma_tf32(float c[4], uint32_t a0, uint32_t a1,
                                         uint32_t a2, uint32_t a3,
                                         uint32_t b0, uint32_t b1) {
    asm volatile(
        "mma.sync.aligned.m16n8k8.row.col.f32.tf32.tf32.f32 "
        "{%0,%1,%2,%3}, {%4,%5,%6,%7}, {%8,%9}, {%0,%1,%2,%3};\n"
        : "+f"(c[0]), "+f"(c[1]), "+f"(c[2]), "+f"(c[3])
        : "r"(a0), "r"(a1), "r"(a2), "r"(a3), "r"(b0), "r"(b1));
}

// ---------------- fp16 helpers (attention) ----------------
__device__ __forceinline__ void mma_f16(float c[4], uint32_t a0, uint32_t a1,
                                        uint32_t a2, uint32_t a3,
                                        uint32_t b0, uint32_t b1) {
    asm volatile(
        "mma.sync.aligned.m16n8k16.row.col.f32.f16.f16.f32 "
        "{%0,%1,%2,%3}, {%4,%5,%6,%7}, {%8,%9}, {%0,%1,%2,%3};\n"
        : "+f"(c[0]), "+f"(c[1]), "+f"(c[2]), "+f"(c[3])
        : "r"(a0), "r"(a1), "r"(a2), "r"(a3), "r"(b0), "r"(b1));
}
__device__ __forceinline__ uint32_t packh2(float lo, float hi) {
    uint32_t r;
    asm("cvt.rn.f16x2.f32 %0, %2, %1;" : "=r"(r) : "f"(lo), "f"(hi));
    return r;
}
__device__ __forceinline__ void ldsm_x4(uint32_t r[4], const __half* p) {
    uint32_t a = (uint32_t)__cvta_generic_to_shared(p);
    asm volatile("ldmatrix.sync.aligned.m8n8.x4.shared.b16 {%0,%1,%2,%3}, [%4];"
                 : "=r"(r[0]), "=r"(r[1]), "=r"(r[2]), "=r"(r[3]) : "r"(a));
}
__device__ __forceinline__ void ldsm_x4_t(uint32_t r[4], const __half* p) {
    uint32_t a = (uint32_t)__cvta_generic_to_shared(p);
    asm volatile("ldmatrix.sync.aligned.m8n8.x4.trans.shared.b16 {%0,%1,%2,%3}, [%4];"
                 : "=r"(r[0]), "=r"(r[1]), "=r"(r[2]), "=r"(r[3]) : "r"(a));
}

// ---------------- tf32 tensor-core GEMM (R7 verbatim — proven best) ----------------
#define BM 128
#define BN 128
#define BK 32
#define LDT 36

__global__ __launch_bounds__(256)
void gemm_tf32(const float* __restrict__ A, const float* __restrict__ Bw,
               const float* __restrict__ bias, float* __restrict__ C,
               int N, int K)
{
    __shared__ float As[BM * LDT];
    __shared__ float Bs[BN * LDT];

    const int tid  = threadIdx.x;
    const int lane = tid & 31;
    const int wid  = tid >> 5;
    const int g = lane >> 2;
    const int t = lane & 3;
    const int wm = wid >> 2;
    const int wn = wid & 3;
    const int row0 = blockIdx.y * BM;
    const int col0 = blockIdx.x * BN;

    const int kg = tid & 7;
    const int lr = tid >> 3;
    const float* Ag = A  + (size_t)(row0 + lr) * K + kg * 4;
    const float* Bg = Bw + (size_t)(col0 + lr) * K + kg * 4;

    float c[4][4][4];
#pragma unroll
    for (int mt = 0; mt < 4; mt++)
#pragma unroll
        for (int nt = 0; nt < 4; nt++)
#pragma unroll
            for (int r = 0; r < 4; r++) c[mt][nt][r] = 0.f;

    const float* Awp = &As[(wm * 64) * LDT];
    const float* Bwp = &Bs[(wn * 32) * LDT];

    for (int kp = 0; kp < K; kp += BK) {
        float4 av[4], bv[4];
#pragma unroll
        for (int i = 0; i < 4; i++) {
            av[i] = *(const float4*)(Ag + (size_t)i * 32 * K + kp);
            bv[i] = *(const float4*)(Bg + (size_t)i * 32 * K + kp);
        }
#pragma unroll
        for (int i = 0; i < 4; i++) {
            av[i].x = __uint_as_float(f2tf32(av[i].x));
            av[i].y = __uint_as_float(f2tf32(av[i].y));
            av[i].z = __uint_as_float(f2tf32(av[i].z));
            av[i].w = __uint_as_float(f2tf32(av[i].w));
            bv[i].x = __uint_as_float(f2tf32(bv[i].x));
            bv[i].y = __uint_as_float(f2tf32(bv[i].y));
            bv[i].z = __uint_as_float(f2tf32(bv[i].z));
            bv[i].w = __uint_as_float(f2tf32(bv[i].w));
        }
        __syncthreads();
#pragma unroll
        for (int i = 0; i < 4; i++) {
            *(float4*)&As[(lr + i * 32) * LDT + kg * 4] = av[i];
            *(float4*)&Bs[(lr + i * 32) * LDT + kg * 4] = bv[i];
        }
        __syncthreads();

#pragma unroll
        for (int kq = 0; kq < BK; kq += 8) {
            uint32_t af[4][4], bf[4][2];
#pragma unroll
            for (int mt = 0; mt < 4; mt++) {
                const float* ap = Awp + (mt * 16 + g) * LDT + kq + t;
                af[mt][0] = __float_as_uint(ap[0]);
                af[mt][1] = __float_as_uint(ap[8 * LDT]);
                af[mt][2] = __float_as_uint(ap[4]);
                af[mt][3] = __float_as_uint(ap[8 * LDT + 4]);
            }
#pragma unroll
            for (int nt = 0; nt < 4; nt++) {
                const float* bp = Bwp + (nt * 8 + g) * LDT + kq + t;
                bf[nt][0] = __float_as_uint(bp[0]);
                bf[nt][1] = __float_as_uint(bp[4]);
            }
#pragma unroll
            for (int mt = 0; mt < 4; mt++)
#pragma unroll
                for (int nt = 0; nt < 4; nt++)
                    mma_tf32(c[mt][nt], af[mt][0], af[mt][1], af[mt][2], af[mt][3],
                             bf[nt][0], bf[nt][1]);
        }
    }

#pragma unroll
    for (int mt = 0; mt < 4; mt++) {
        int row = row0 + wm * 64 + mt * 16 + g;
#pragma unroll
        for (int nt = 0; nt < 4; nt++) {
            int col = col0 + wn * 32 + nt * 8 + 2 * t;
            float b0 = bias[col], b1 = bias[col + 1];
            float2 v0 = make_float2(c[mt][nt][0] + b0, c[mt][nt][1] + b1);
            float2 v1 = make_float2(c[mt][nt][2] + b0, c[mt][nt][3] + b1);
            *(float2*)&C[(size_t)row * N + col] = v0;
            *(float2*)&C[(size_t)(row + 8) * N + col] = v1;
        }
    }
}

// ---------------- fp16-split flash attention, ldmatrix fragment loads ----------------
// CTA: 128 queries x 64-key tiles, 8 warps (16 query rows each).
// QK^T: 3-term fp16 split. PV: P fp16, V 2-term split. All fragment loads via ldmatrix.
#define SH 72                       // smem row stride in halves (144 B)
#define OQH 0
#define OQL (128 * SH)
#define OKH (2 * 128 * SH)
#define OKL (OKH + 64 * SH)
#define OVH (OKL + 64 * SH)
#define OVL (OVH + 64 * SH)
#define OPS (OVL + 64 * SH)
#define SMH_TOT (OPS + 128 * SH)    // 46080 halves = 92160 B

__global__ __launch_bounds__(256, 2)
void attn_fp16(const float* __restrict__ qkv, float* __restrict__ attn_out)
{
    extern __shared__ __half smh[];

    const int tid  = threadIdx.x;
    const int lane = tid & 31;
    const int w = tid >> 5;
    const int g = lane >> 2;
    const int t = lane & 3;
    const int b = blockIdx.y >> 4, h = blockIdx.y & 15;
    const int qt = (int)gridDim.x - 1 - (int)blockIdx.x;   // heavy CTAs first
    const int q0 = qt * 128;
    const float* base = qkv + (size_t)b * SEQ * QKV_N + h * (3 * HEAD_DIM);
    const float SC = 0.125f * 1.4426950408889634f;   // 1/sqrt(hd) * log2(e)

    // ---- load Q tile, split into fp16 hi/lo ----
#pragma unroll
    for (int i = 0; i < 8; i++) {
        int idx = tid + i * 256;
        int r = idx >> 4, c4 = (idx & 15) << 2;
        float4 q = *(const float4*)(base + (size_t)(q0 + r) * QKV_N + c4);
        float f[4] = {q.x * SC, q.y * SC, q.z * SC, q.w * SC};
        float hh[4], ll[4];
#pragma unroll
        for (int e = 0; e < 4; e++) {
            hh[e] = __half2float(__float2half_rn(f[e]));
            ll[e] = f[e] - hh[e];
        }
        uint32_t* ph = (uint32_t*)&smh[OQH + r * SH + c4];
        uint32_t* pl = (uint32_t*)&smh[OQL + r * SH + c4];
        ph[0] = packh2(hh[0], hh[1]); ph[1] = packh2(hh[2], hh[3]);
        pl[0] = packh2(ll[0], ll[1]); pl[1] = packh2(ll[2], ll[3]);
    }

    float o[8][4];
#pragma unroll
    for (int nt = 0; nt < 8; nt++)
#pragma unroll
        for (int r = 0; r < 4; r++) o[nt][r] = 0.f;
    float m0 = -1e30f, m1 = -1e30f, l0 = 0.f, l1 = 0.f;

    const int wr = w * 16;
    const int myrow = q0 + wr;
    const int rowg0 = myrow + g, rowg1 = myrow + g + 8;
    const int nkt = qt * 2 + 2;

    // ldmatrix per-thread selectors
    const int lr7  = lane & 7;        // row within 8-row matrix
    const int mi   = lane >> 3;       // matrix index 0..3
    const int ksel = (lane >> 3) & 1; // for V trans loads (unchanged)
    const int nsel = lane >> 4;
    // A/P-frag address: matrices (rows g | g+8) x (k-lo | k-hi)
    const int a_base = (wr + lr7 + 8 * (mi & 1)) * SH + 8 * (mi >> 1);
    // B(K)-frag address for nt-pair p: matrices (nt=2p | 2p+1) x (k-lo | k-hi)
    const int b_row  = lr7 * SH + 8 * (mi & 1);
    const int b_pairstep = 16 * SH;   // 2 nt tiles = 16 key rows
    const int b_mihalf = (mi >> 1) * 8 * SH;

    for (int j = 0; j < nkt; j++) {
        const int k0 = j * 64;
        // register prefetch of K/V tile
        float4 kk[4], vv[4];
#pragma unroll
        for (int i = 0; i < 4; i++) {
            int idx = tid + i * 256;
            int r = idx >> 4, c4 = (idx & 15) << 2;
            const float* rp = base + (size_t)(k0 + r) * QKV_N + c4;
            kk[i] = *(const float4*)(rp + HEAD_DIM);
            vv[i] = *(const float4*)(rp + 2 * HEAD_DIM);
        }
        __syncthreads();   // previous tile fully consumed
#pragma unroll
        for (int i = 0; i < 4; i++) {
            int idx = tid + i * 256;
            int r = idx >> 4, c4 = (idx & 15) << 2;
            float kf[4] = {kk[i].x, kk[i].y, kk[i].z, kk[i].w};
            float vf[4] = {vv[i].x, vv[i].y, vv[i].z, vv[i].w};
            float kh[4], kl[4], vh[4], vl[4];
#pragma unroll
            for (int e = 0; e < 4; e++) {
                kh[e] = __half2float(__float2half_rn(kf[e])); kl[e] = kf[e] - kh[e];
                vh[e] = __half2float(__float2half_rn(vf[e])); vl[e] = vf[e] - vh[e];
            }
            uint32_t* p;
            p = (uint32_t*)&smh[OKH + r * SH + c4];
            p[0] = packh2(kh[0], kh[1]); p[1] = packh2(kh[2], kh[3]);
            p = (uint32_t*)&smh[OKL + r * SH + c4];
            p[0] = packh2(kl[0], kl[1]); p[1] = packh2(kl[2], kl[3]);
            p = (uint32_t*)&smh[OVH + r * SH + c4];
            p[0] = packh2(vh[0], vh[1]); p[1] = packh2(vh[2], vh[3]);
            p = (uint32_t*)&smh[OVL + r * SH + c4];
            p[0] = packh2(vl[0], vl[1]); p[1] = packh2(vl[2], vl[3]);
        }
        __syncthreads();

        if (k0 <= myrow + 15) {   // not fully masked for this warp
            // ---- S = Q K^T  (3-term fp16 split, ldmatrix frags) ----
            float s[8][4];
#pragma unroll
            for (int nt = 0; nt < 8; nt++)
#pragma unroll
                for (int r = 0; r < 4; r++) s[nt][r] = 0.f;

#pragma unroll
            for (int kq = 0; kq < 4; kq++) {
                const int kc = kq * 16;
                uint32_t ah[4], al[4];
                ldsm_x4(ah, &smh[OQH + a_base + kc]);
                ldsm_x4(al, &smh[OQL + a_base + kc]);
#pragma unroll
                for (int p = 0; p < 4; p++) {
                    uint32_t bh[4], bl[4];
                    ldsm_x4(bh, &smh[OKH + b_row + p * b_pairstep + b_mihalf + kc]);
                    ldsm_x4(bl, &smh[OKL + b_row + p * b_pairstep + b_mihalf + kc]);
                    mma_f16(s[2 * p],     ah[0], ah[1], ah[2], ah[3], bh[0], bh[1]);
                    mma_f16(s[2 * p],     al[0], al[1], al[2], al[3], bh[0], bh[1]);
                    mma_f16(s[2 * p],     ah[0], ah[1], ah[2], ah[3], bl[0], bl[1]);
                    mma_f16(s[2 * p + 1], ah[0], ah[1], ah[2], ah[3], bh[2], bh[3]);
                    mma_f16(s[2 * p + 1], al[0], al[1], al[2], al[3], bh[2], bh[3]);
                    mma_f16(s[2 * p + 1], ah[0], ah[1], ah[2], ah[3], bl[2], bl[3]);
                }
            }

            // ---- causal mask (diagonal-straddling tiles only) ----
            if (k0 + 63 > myrow) {
#pragma unroll
                for (int nt = 0; nt < 8; nt++) {
                    int c = k0 + nt * 8 + 2 * t;
                    if (c > rowg0)     s[nt][0] = -1e30f;
                    if (c + 1 > rowg0) s[nt][1] = -1e30f;
                    if (c > rowg1)     s[nt][2] = -1e30f;
                    if (c + 1 > rowg1) s[nt][3] = -1e30f;
                }
            }

            // ---- online softmax (exp2 domain), P -> fp16 smem ----
            float rm0 = -1e30f, rm1 = -1e30f;
#pragma unroll
            for (int nt = 0; nt < 8; nt++) {
                rm0 = fmaxf(rm0, fmaxf(s[nt][0], s[nt][1]));
                rm1 = fmaxf(rm1, fmaxf(s[nt][2], s[nt][3]));
            }
            rm0 = fmaxf(rm0, __shfl_xor_sync(0xffffffffu, rm0, 1));
            rm0 = fmaxf(rm0, __shfl_xor_sync(0xffffffffu, rm0, 2));
            rm1 = fmaxf(rm1, __shfl_xor_sync(0xffffffffu, rm1, 1));
            rm1 = fmaxf(rm1, __shfl_xor_sync(0xffffffffu, rm1, 2));
            float mn0 = fmaxf(m0, rm0), mn1 = fmaxf(m1, rm1);
            float alp0 = exp2f(m0 - mn0), alp1 = exp2f(m1 - mn1);
            float rs0 = 0.f, rs1 = 0.f;
#pragma unroll
            for (int nt = 0; nt < 8; nt++) {
                s[nt][0] = exp2f(s[nt][0] - mn0);
                s[nt][1] = exp2f(s[nt][1] - mn0);
                s[nt][2] = exp2f(s[nt][2] - mn1);
                s[nt][3] = exp2f(s[nt][3] - mn1);
                rs0 += s[nt][0] + s[nt][1];
                rs1 += s[nt][2] + s[nt][3];
                *(uint32_t*)&smh[OPS + (wr + g) * SH + nt * 8 + 2 * t] =
                    packh2(s[nt][0], s[nt][1]);
                *(uint32_t*)&smh[OPS + (wr + g + 8) * SH + nt * 8 + 2 * t] =
                    packh2(s[nt][2], s[nt][3]);
            }
            rs0 += __shfl_xor_sync(0xffffffffu, rs0, 1);
            rs0 += __shfl_xor_sync(0xffffffffu, rs0, 2);
            rs1 += __shfl_xor_sync(0xffffffffu, rs1, 1);
            rs1 += __shfl_xor_sync(0xffffffffu, rs1, 2);
            l0 = l0 * alp0 + rs0;  l1 = l1 * alp1 + rs1;
            m0 = mn0;  m1 = mn1;
#pragma unroll
            for (int nt = 0; nt < 8; nt++) {
                o[nt][0] *= alp0; o[nt][1] *= alp0;
                o[nt][2] *= alp1; o[nt][3] *= alp1;
            }
            __syncwarp();   // P stores visible to warp

            // ---- O += P V  (P via ldmatrix; V^T via ldmatrix.trans) ----
#pragma unroll
            for (int kq = 0; kq < 4; kq++) {
                const int kc = kq * 16;
                uint32_t pa[4];
                ldsm_x4(pa, &smh[OPS + a_base + kc]);
                const int vrow = (kc + lr7 + 8 * ksel) * SH + nsel * 8;
#pragma unroll
                for (int np = 0; np < 4; np++) {
                    uint32_t bh[4], bl[4];
                    ldsm_x4_t(bh, &smh[OVH + vrow + np * 16]);
                    ldsm_x4_t(bl, &smh[OVL + vrow + np * 16]);
                    mma_f16(o[np * 2],     pa[0], pa[1], pa[2], pa[3], bh[0], bh[1]);
                    mma_f16(o[np * 2],     pa[0], pa[1], pa[2], pa[3], bl[0], bl[1]);
                    mma_f16(o[np * 2 + 1], pa[0], pa[1], pa[2], pa[3], bh[2], bh[3]);
                    mma_f16(o[np * 2 + 1], pa[0], pa[1], pa[2], pa[3], bl[2], bl[3]);
                }
            }
            __syncwarp();
        }
    }

    // ---- normalize + write [B,H,S,hd] ----
    float inv0 = 1.0f / l0, inv1 = 1.0f / l1;
    float* op = attn_out + ((size_t)b * NUM_HEADS + h) * SEQ * HEAD_DIM;
#pragma unroll
    for (int nt = 0; nt < 8; nt++) {
        int c = nt * 8 + 2 * t;
        *(float2*)&op[(size_t)rowg0 * HEAD_DIM + c] =
            make_float2(o[nt][0] * inv0, o[nt][1] * inv0);
        *(float2*)&op[(size_t)rowg1 * HEAD_DIM + c] =
            make_float2(o[nt][2] * inv1, o[nt][3] * inv1);
    }
}

// ---------------- launch ----------------
extern "C" void kernel_launch(void* const* d_in, const int* in_sizes, int n_in,
                              void* d_out, int out_size)
{
    const float* x    = (const float*)d_in[0];
    const float* Wqkv = (const float*)d_in[1];
    const float* bqkv = (const float*)d_in[2];
    const float* Wo   = (const float*)d_in[3];
    const float* bo   = (const float*)d_in[4];
    float* out = (float*)d_out;

    float* qkv_ptr = nullptr;
    float* attn_ptr = nullptr;
    cudaGetSymbolAddress((void**)&qkv_ptr, g_qkv);
    cudaGetSymbolAddress((void**)&attn_ptr, g_attn);

    const int attn_smem = SMH_TOT * (int)sizeof(__half);   // 92160 B
    cudaFuncSetAttribute(attn_fp16, cudaFuncAttributeMaxDynamicSharedMemorySize, attn_smem);

    // 1) qkv = x @ Wqkv^T + bqkv   (tf32 tensor cores)
    gemm_tf32<<<dim3(QKV_N / BN, M_TOT / BM), 256>>>(x, Wqkv, bqkv, qkv_ptr, QKV_N, D_MODEL);
    // 2) causal flash attention (fp16-split, ldmatrix fragment loads)
    attn_fp16<<<dim3(SEQ / 128, BATCH * NUM_HEADS), 256, attn_smem>>>(qkv_ptr, attn_ptr);
    // 3) out = attn @ Wo^T + bo    (tf32 tensor cores)
    gemm_tf32<<<dim3(D_MODEL / BN, M_TOT / BM), 256>>>(attn_ptr, Wo, bo, out, D_MODEL, D_MODEL);
}

// round 14
// speedup vs baseline: 1.8735x; 1.1777x over previous
#include <cuda_runtime.h>
#include <cuda_fp16.h>
#include <cstdint>

// ---------------- problem constants ----------------
#define D_MODEL   1024
#define NUM_HEADS 16
#define HEAD_DIM  64
#define BATCH     2
#define SEQ       2048
#define M_TOT     (BATCH * SEQ)      // 4096
#define QKV_N     (3 * D_MODEL)      // 3072

// scratch (no cudaMalloc allowed)
__device__ float g_qkv[(size_t)M_TOT * QKV_N];      // [B,S,3D]
__device__ float g_attn[(size_t)M_TOT * D_MODEL];   // [B,H,S,hd] == reshape(B,S,D)

// ---------------- fp16 helpers ----------------
__device__ __forceinline__ void mma_f16(float c[4], uint32_t a0, uint32_t a1,
                                        uint32_t a2, uint32_t a3,
                                        uint32_t b0, uint32_t b1) {
    asm volatile(
        "mma.sync.aligned.m16n8k16.row.col.f32.f16.f16.f32 "
        "{%0,%1,%2,%3}, {%4,%5,%6,%7}, {%8,%9}, {%0,%1,%2,%3};\n"
        : "+f"(c[0]), "+f"(c[1]), "+f"(c[2]), "+f"(c[3])
        : "r"(a0), "r"(a1), "r"(a2), "r"(a3), "r"(b0), "r"(b1));
}
__device__ __forceinline__ uint32_t packh2(float lo, float hi) {
    uint32_t r;
    asm("cvt.rn.f16x2.f32 %0, %2, %1;" : "=r"(r) : "f"(lo), "f"(hi));
    return r;
}
__device__ __forceinline__ void ldsm_x4(uint32_t r[4], const __half* p) {
    uint32_t a = (uint32_t)__cvta_generic_to_shared(p);
    asm volatile("ldmatrix.sync.aligned.m8n8.x4.shared.b16 {%0,%1,%2,%3}, [%4];"
                 : "=r"(r[0]), "=r"(r[1]), "=r"(r[2]), "=r"(r[3]) : "r"(a));
}
__device__ __forceinline__ void ldsm_x4_t(uint32_t r[4], const __half* p) {
    uint32_t a = (uint32_t)__cvta_generic_to_shared(p);
    asm volatile("ldmatrix.sync.aligned.m8n8.x4.trans.shared.b16 {%0,%1,%2,%3}, [%4];"
                 : "=r"(r[0]), "=r"(r[1]), "=r"(r[2]), "=r"(r[3]) : "r"(a));
}

// ---------------- fp16 tensor-core GEMM: C[M,N] = A[M,K] * Bw[N,K]^T + bias ----------------
// 128x128x32 CTA tile, 256 threads (8 warps), warp tile 64x32 = 4x4 m16n8k16.
// fp16 operands (e5m10 == tf32's mantissa) -> half the MMA count of tf32 k8.
#define BM 128
#define BN 128
#define BK 32
#define LDH 40            // smem row stride in halves (80 B): ldmatrix rows 5r mod 8 conflict-free

__global__ __launch_bounds__(256, 2)
void gemm_f16(const float* __restrict__ A, const float* __restrict__ Bw,
              const float* __restrict__ bias, float* __restrict__ C,
              int N, int K)
{
    __shared__ __half As[BM * LDH];
    __shared__ __half Bs[BN * LDH];

    const int tid  = threadIdx.x;
    const int lane = tid & 31;
    const int wid  = tid >> 5;
    const int g = lane >> 2;
    const int t = lane & 3;
    const int wm = wid >> 2;      // 0..1 -> 64 rows
    const int wn = wid & 3;       // 0..3 -> 32 cols
    const int row0 = blockIdx.y * BM;
    const int col0 = blockIdx.x * BN;

    // ldmatrix selectors (same proven mappings as the attention kernel)
    const int lr7 = lane & 7;
    const int mi  = lane >> 3;
    const int a_off = (lr7 + 8 * (mi & 1)) * LDH + 8 * (mi >> 1);
    const int b_off = lr7 * LDH + 8 * (mi & 1) + (mi >> 1) * 8 * LDH;

    // staging loader: kg = float4 index along K-panel (0..7), lr = row 0..31 (+32i)
    const int kg = tid & 7;
    const int lr = tid >> 3;
    const float* Ag = A  + (size_t)(row0 + lr) * K + kg * 4;
    const float* Bg = Bw + (size_t)(col0 + lr) * K + kg * 4;

    float c[4][4][4];
#pragma unroll
    for (int mt = 0; mt < 4; mt++)
#pragma unroll
        for (int nt = 0; nt < 4; nt++)
#pragma unroll
            for (int r = 0; r < 4; r++) c[mt][nt][r] = 0.f;

    const __half* Awp = &As[(wm * 64) * LDH];
    const __half* Bwp = &Bs[(wn * 32) * LDH];

    for (int kp = 0; kp < K; kp += BK) {
        // register prefetch + fp16 convert (overlaps previous panel's compute)
        float4 av[4], bv[4];
#pragma unroll
        for (int i = 0; i < 4; i++) {
            av[i] = *(const float4*)(Ag + (size_t)i * 32 * K + kp);
            bv[i] = *(const float4*)(Bg + (size_t)i * 32 * K + kp);
        }
        uint2 ap[4], bp[4];
#pragma unroll
        for (int i = 0; i < 4; i++) {
            ap[i] = make_uint2(packh2(av[i].x, av[i].y), packh2(av[i].z, av[i].w));
            bp[i] = make_uint2(packh2(bv[i].x, bv[i].y), packh2(bv[i].z, bv[i].w));
        }
        __syncthreads();   // previous panel fully consumed
#pragma unroll
        for (int i = 0; i < 4; i++) {
            *(uint2*)&As[(lr + i * 32) * LDH + kg * 4] = ap[i];
            *(uint2*)&Bs[(lr + i * 32) * LDH + kg * 4] = bp[i];
        }
        __syncthreads();

#pragma unroll
        for (int kq = 0; kq < BK; kq += 16) {
            uint32_t af[4][4];
#pragma unroll
            for (int mt = 0; mt < 4; mt++)
                ldsm_x4(af[mt], Awp + mt * 16 * LDH + a_off + kq);
#pragma unroll
            for (int p = 0; p < 2; p++) {
                uint32_t bf[4];
                ldsm_x4(bf, Bwp + p * 16 * LDH + b_off + kq);
#pragma unroll
                for (int mt = 0; mt < 4; mt++) {
                    mma_f16(c[mt][2 * p],     af[mt][0], af[mt][1], af[mt][2], af[mt][3],
                            bf[0], bf[1]);
                    mma_f16(c[mt][2 * p + 1], af[mt][0], af[mt][1], af[mt][2], af[mt][3],
                            bf[2], bf[3]);
                }
            }
        }
    }

    // epilogue: bias + store (same accumulator layout as k8)
#pragma unroll
    for (int mt = 0; mt < 4; mt++) {
        int row = row0 + wm * 64 + mt * 16 + g;
#pragma unroll
        for (int nt = 0; nt < 4; nt++) {
            int col = col0 + wn * 32 + nt * 8 + 2 * t;
            float b0 = bias[col], b1 = bias[col + 1];
            float2 v0 = make_float2(c[mt][nt][0] + b0, c[mt][nt][1] + b1);
            float2 v1 = make_float2(c[mt][nt][2] + b0, c[mt][nt][3] + b1);
            *(float2*)&C[(size_t)row * N + col] = v0;
            *(float2*)&C[(size_t)(row + 8) * N + col] = v1;
        }
    }
}

// ---------------- fp16-split flash attention, ldmatrix fragment loads (R13) ----------------
#define SH 72                       // smem row stride in halves (144 B)
#define OQH 0
#define OQL (128 * SH)
#define OKH (2 * 128 * SH)
#define OKL (OKH + 64 * SH)
#define OVH (OKL + 64 * SH)
#define OVL (OVH + 64 * SH)
#define OPS (OVL + 64 * SH)
#define SMH_TOT (OPS + 128 * SH)    // 46080 halves = 92160 B

__global__ __launch_bounds__(256, 2)
void attn_fp16(const float* __restrict__ qkv, float* __restrict__ attn_out)
{
    extern __shared__ __half smh[];

    const int tid  = threadIdx.x;
    const int lane = tid & 31;
    const int w = tid >> 5;
    const int g = lane >> 2;
    const int t = lane & 3;
    const int b = blockIdx.y >> 4, h = blockIdx.y & 15;
    const int qt = (int)gridDim.x - 1 - (int)blockIdx.x;   // heavy CTAs first
    const int q0 = qt * 128;
    const float* base = qkv + (size_t)b * SEQ * QKV_N + h * (3 * HEAD_DIM);
    const float SC = 0.125f * 1.4426950408889634f;   // 1/sqrt(hd) * log2(e)

    // ---- load Q tile, split into fp16 hi/lo ----
#pragma unroll
    for (int i = 0; i < 8; i++) {
        int idx = tid + i * 256;
        int r = idx >> 4, c4 = (idx & 15) << 2;
        float4 q = *(const float4*)(base + (size_t)(q0 + r) * QKV_N + c4);
        float f[4] = {q.x * SC, q.y * SC, q.z * SC, q.w * SC};
        float hh[4], ll[4];
#pragma unroll
        for (int e = 0; e < 4; e++) {
            hh[e] = __half2float(__float2half_rn(f[e]));
            ll[e] = f[e] - hh[e];
        }
        uint32_t* ph = (uint32_t*)&smh[OQH + r * SH + c4];
        uint32_t* pl = (uint32_t*)&smh[OQL + r * SH + c4];
        ph[0] = packh2(hh[0], hh[1]); ph[1] = packh2(hh[2], hh[3]);
        pl[0] = packh2(ll[0], ll[1]); pl[1] = packh2(ll[2], ll[3]);
    }

    float o[8][4];
#pragma unroll
    for (int nt = 0; nt < 8; nt++)
#pragma unroll
        for (int r = 0; r < 4; r++) o[nt][r] = 0.f;
    float m0 = -1e30f, m1 = -1e30f, l0 = 0.f, l1 = 0.f;

    const int wr = w * 16;
    const int myrow = q0 + wr;
    const int rowg0 = myrow + g, rowg1 = myrow + g + 8;
    const int nkt = qt * 2 + 2;

    const int lr7  = lane & 7;
    const int mi   = lane >> 3;
    const int ksel = (lane >> 3) & 1;
    const int nsel = lane >> 4;
    const int a_base = (wr + lr7 + 8 * (mi & 1)) * SH + 8 * (mi >> 1);
    const int b_row  = lr7 * SH + 8 * (mi & 1);
    const int b_pairstep = 16 * SH;
    const int b_mihalf = (mi >> 1) * 8 * SH;

    for (int j = 0; j < nkt; j++) {
        const int k0 = j * 64;
        float4 kk[4], vv[4];
#pragma unroll
        for (int i = 0; i < 4; i++) {
            int idx = tid + i * 256;
            int r = idx >> 4, c4 = (idx & 15) << 2;
            const float* rp = base + (size_t)(k0 + r) * QKV_N + c4;
            kk[i] = *(const float4*)(rp + HEAD_DIM);
            vv[i] = *(const float4*)(rp + 2 * HEAD_DIM);
        }
        __syncthreads();
#pragma unroll
        for (int i = 0; i < 4; i++) {
            int idx = tid + i * 256;
            int r = idx >> 4, c4 = (idx & 15) << 2;
            float kf[4] = {kk[i].x, kk[i].y, kk[i].z, kk[i].w};
            float vf[4] = {vv[i].x, vv[i].y, vv[i].z, vv[i].w};
            float kh[4], kl[4], vh[4], vl[4];
#pragma unroll
            for (int e = 0; e < 4; e++) {
                kh[e] = __half2float(__float2half_rn(kf[e])); kl[e] = kf[e] - kh[e];
                vh[e] = __half2float(__float2half_rn(vf[e])); vl[e] = vf[e] - vh[e];
            }
            uint32_t* p;
            p = (uint32_t*)&smh[OKH + r * SH + c4];
            p[0] = packh2(kh[0], kh[1]); p[1] = packh2(kh[2], kh[3]);
            p = (uint32_t*)&smh[OKL + r * SH + c4];
            p[0] = packh2(kl[0], kl[1]); p[1] = packh2(kl[2], kl[3]);
            p = (uint32_t*)&smh[OVH + r * SH + c4];
            p[0] = packh2(vh[0], vh[1]); p[1] = packh2(vh[2], vh[3]);
            p = (uint32_t*)&smh[OVL + r * SH + c4];
            p[0] = packh2(vl[0], vl[1]); p[1] = packh2(vl[2], vl[3]);
        }
        __syncthreads();

        if (k0 <= myrow + 15) {
            float s[8][4];
#pragma unroll
            for (int nt = 0; nt < 8; nt++)
#pragma unroll
                for (int r = 0; r < 4; r++) s[nt][r] = 0.f;

#pragma unroll
            for (int kq = 0; kq < 4; kq++) {
                const int kc = kq * 16;
                uint32_t ah[4], al[4];
                ldsm_x4(ah, &smh[OQH + a_base + kc]);
                ldsm_x4(al, &smh[OQL + a_base + kc]);
#pragma unroll
                for (int p = 0; p < 4; p++) {
                    uint32_t bh[4], bl[4];
                    ldsm_x4(bh, &smh[OKH + b_row + p * b_pairstep + b_mihalf + kc]);
                    ldsm_x4(bl, &smh[OKL + b_row + p * b_pairstep + b_mihalf + kc]);
                    mma_f16(s[2 * p],     ah[0], ah[1], ah[2], ah[3], bh[0], bh[1]);
                    mma_f16(s[2 * p],     al[0], al[1], al[2], al[3], bh[0], bh[1]);
                    mma_f16(s[2 * p],     ah[0], ah[1], ah[2], ah[3], bl[0], bl[1]);
                    mma_f16(s[2 * p + 1], ah[0], ah[1], ah[2], ah[3], bh[2], bh[3]);
                    mma_f16(s[2 * p + 1], al[0], al[1], al[2], al[3], bh[2], bh[3]);
                    mma_f16(s[2 * p + 1], ah[0], ah[1], ah[2], ah[3], bl[2], bl[3]);
                }
            }

            if (k0 + 63 > myrow) {
#pragma unroll
                for (int nt = 0; nt < 8; nt++) {
                    int c = k0 + nt * 8 + 2 * t;
                    if (c > rowg0)     s[nt][0] = -1e30f;
                    if (c + 1 > rowg0) s[nt][1] = -1e30f;
                    if (c > rowg1)     s[nt][2] = -1e30f;
                    if (c + 1 > rowg1) s[nt][3] = -1e30f;
                }
            }

            float rm0 = -1e30f, rm1 = -1e30f;
#pragma unroll
            for (int nt = 0; nt < 8; nt++) {
                rm0 = fmaxf(rm0, fmaxf(s[nt][0], s[nt][1]));
                rm1 = fmaxf(rm1, fmaxf(s[nt][2], s[nt][3]));
            }
            rm0 = fmaxf(rm0, __shfl_xor_sync(0xffffffffu, rm0, 1));
            rm0 = fmaxf(rm0, __shfl_xor_sync(0xffffffffu, rm0, 2));
            rm1 = fmaxf(rm1, __shfl_xor_sync(0xffffffffu, rm1, 1));
            rm1 = fmaxf(rm1, __shfl_xor_sync(0xffffffffu, rm1, 2));
            float mn0 = fmaxf(m0, rm0), mn1 = fmaxf(m1, rm1);
            float alp0 = exp2f(m0 - mn0), alp1 = exp2f(m1 - mn1);
            float rs0 = 0.f, rs1 = 0.f;
#pragma unroll
            for (int nt = 0; nt < 8; nt++) {
                s[nt][0] = exp2f(s[nt][0] - mn0);
                s[nt][1] = exp2f(s[nt][1] - mn0);
                s[nt][2] = exp2f(s[nt][2] - mn1);
                s[nt][3] = exp2f(s[nt][3] - mn1);
                rs0 += s[nt][0] + s[nt][1];
                rs1 += s[nt][2] + s[nt][3];
                *(uint32_t*)&smh[OPS + (wr + g) * SH + nt * 8 + 2 * t] =
                    packh2(s[nt][0], s[nt][1]);
                *(uint32_t*)&smh[OPS + (wr + g + 8) * SH + nt * 8 + 2 * t] =
                    packh2(s[nt][2], s[nt][3]);
            }
            rs0 += __shfl_xor_sync(0xffffffffu, rs0, 1);
            rs0 += __shfl_xor_sync(0xffffffffu, rs0, 2);
            rs1 += __shfl_xor_sync(0xffffffffu, rs1, 1);
            rs1 += __shfl_xor_sync(0xffffffffu, rs1, 2);
            l0 = l0 * alp0 + rs0;  l1 = l1 * alp1 + rs1;
            m0 = mn0;  m1 = mn1;
#pragma unroll
            for (int nt = 0; nt < 8; nt++) {
                o[nt][0] *= alp0; o[nt][1] *= alp0;
                o[nt][2] *= alp1; o[nt][3] *= alp1;
            }
            __syncwarp();

#pragma unroll
            for (int kq = 0; kq < 4; kq++) {
                const int kc = kq * 16;
                uint32_t pa[4];
                ldsm_x4(pa, &smh[OPS + a_base + kc]);
                const int vrow = (kc + lr7 + 8 * ksel) * SH + nsel * 8;
#pragma unroll
                for (int np = 0; np < 4; np++) {
                    uint32_t bh[4], bl[4];
                    ldsm_x4_t(bh, &smh[OVH + vrow + np * 16]);
                    ldsm_x4_t(bl, &smh[OVL + vrow + np * 16]);
                    mma_f16(o[np * 2],     pa[0], pa[1], pa[2], pa[3], bh[0], bh[1]);
                    mma_f16(o[np * 2],     pa[0], pa[1], pa[2], pa[3], bl[0], bl[1]);
                    mma_f16(o[np * 2 + 1], pa[0], pa[1], pa[2], pa[3], bh[2], bh[3]);
                    mma_f16(o[np * 2 + 1], pa[0], pa[1], pa[2], pa[3], bl[2], bl[3]);
                }
            }
            __syncwarp();
        }
    }

    // ---- normalize + write [B,H,S,hd] ----
    float inv0 = 1.0f / l0, inv1 = 1.0f / l1;
    float* op = attn_out + ((size_t)b * NUM_HEADS + h) * SEQ * HEAD_DIM;
#pragma unroll
    for (int nt = 0; nt < 8; nt++) {
        int c = nt * 8 + 2 * t;
        *(float2*)&op[(size_t)rowg0 * HEAD_DIM + c] =
            make_float2(o[nt][0] * inv0, o[nt][1] * inv0);
        *(float2*)&op[(size_t)rowg1 * HEAD_DIM + c] =
            make_float2(o[nt][2] * inv1, o[nt][3] * inv1);
    }
}

// ---------------- launch ----------------
extern "C" void kernel_launch(void* const* d_in, const int* in_sizes, int n_in,
                              void* d_out, int out_size)
{
    const float* x    = (const float*)d_in[0];
    const float* Wqkv = (const float*)d_in[1];
    const float* bqkv = (const float*)d_in[2];
    const float* Wo   = (const float*)d_in[3];
    const float* bo   = (const float*)d_in[4];
    float* out = (float*)d_out;

    float* qkv_ptr = nullptr;
    float* attn_ptr = nullptr;
    cudaGetSymbolAddress((void**)&qkv_ptr, g_qkv);
    cudaGetSymbolAddress((void**)&attn_ptr, g_attn);

    const int attn_smem = SMH_TOT * (int)sizeof(__half);   // 92160 B
    cudaFuncSetAttribute(attn_fp16, cudaFuncAttributeMaxDynamicSharedMemorySize, attn_smem);

    // 1) qkv = x @ Wqkv^T + bqkv   (fp16 m16n8k16 tensor cores)
    gemm_f16<<<dim3(QKV_N / BN, M_TOT / BM), 256>>>(x, Wqkv, bqkv, qkv_ptr, QKV_N, D_MODEL);
    // 2) causal flash attention (fp16-split, ldmatrix fragment loads)
    attn_fp16<<<dim3(SEQ / 128, BATCH * NUM_HEADS), 256, attn_smem>>>(qkv_ptr, attn_ptr);
    // 3) out = attn @ Wo^T + bo    (fp16 m16n8k16 tensor cores)
    gemm_f16<<<dim3(D_MODEL / BN, M_TOT / BM), 256>>>(attn_ptr, Wo, bo, out, D_MODEL, D_MODEL);
}

// round 16
// speedup vs baseline: 2.1990x; 1.1738x over previous
#include <cuda_runtime.h>
#include <cuda_fp16.h>
#include <cstdint>

// ---------------- problem constants ----------------
#define D_MODEL   1024
#define NUM_HEADS 16
#define HEAD_DIM  64
#define BATCH     2
#define SEQ       2048
#define M_TOT     (BATCH * SEQ)      // 4096
#define QKV_N     (3 * D_MODEL)      // 3072

// scratch (no cudaMalloc allowed)
__device__ float g_qkv[(size_t)M_TOT * QKV_N];      // [B,S,3D]
__device__ float g_attn[(size_t)M_TOT * D_MODEL];   // [B,H,S,hd] == reshape(B,S,D)

// ---------------- fp16 helpers ----------------
__device__ __forceinline__ void mma_f16(float c[4], uint32_t a0, uint32_t a1,
                                        uint32_t a2, uint32_t a3,
                                        uint32_t b0, uint32_t b1) {
    asm volatile(
        "mma.sync.aligned.m16n8k16.row.col.f32.f16.f16.f32 "
        "{%0,%1,%2,%3}, {%4,%5,%6,%7}, {%8,%9}, {%0,%1,%2,%3};\n"
        : "+f"(c[0]), "+f"(c[1]), "+f"(c[2]), "+f"(c[3])
        : "r"(a0), "r"(a1), "r"(a2), "r"(a3), "r"(b0), "r"(b1));
}
__device__ __forceinline__ uint32_t packh2(float lo, float hi) {
    uint32_t r;
    asm("cvt.rn.f16x2.f32 %0, %2, %1;" : "=r"(r) : "f"(lo), "f"(hi));
    return r;
}
__device__ __forceinline__ void ldsm_x4(uint32_t r[4], const __half* p) {
    uint32_t a = (uint32_t)__cvta_generic_to_shared(p);
    asm volatile("ldmatrix.sync.aligned.m8n8.x4.shared.b16 {%0,%1,%2,%3}, [%4];"
                 : "=r"(r[0]), "=r"(r[1]), "=r"(r[2]), "=r"(r[3]) : "r"(a));
}
__device__ __forceinline__ void ldsm_x4_t(uint32_t r[4], const __half* p) {
    uint32_t a = (uint32_t)__cvta_generic_to_shared(p);
    asm volatile("ldmatrix.sync.aligned.m8n8.x4.trans.shared.b16 {%0,%1,%2,%3}, [%4];"
                 : "=r"(r[0]), "=r"(r[1]), "=r"(r[2]), "=r"(r[3]) : "r"(a));
}

// ---------------- fp16 tensor-core GEMM: C[M,N] = A[M,K] * Bw[N,K]^T + bias ----------------
// 128x128x64 CTA tile, 256 threads (8 warps), warp tile 64x32 = 4x4 m16n8k16.
// BK=64: halves the panel/sync count vs BK=32 -> exposed gmem latency amortized
// over 2x the MMA work per panel.
#define BM 128
#define BN 128
#define BK 64
#define LDH 72            // smem row stride in halves (144 B): ldsm rows 9r mod 8 conflict-free

__global__ __launch_bounds__(256, 2)
void gemm_f16(const float* __restrict__ A, const float* __restrict__ Bw,
              const float* __restrict__ bias, float* __restrict__ C,
              int N, int K)
{
    __shared__ __half As[BM * LDH];
    __shared__ __half Bs[BN * LDH];

    const int tid  = threadIdx.x;
    const int lane = tid & 31;
    const int wid  = tid >> 5;
    const int g = lane >> 2;
    const int t = lane & 3;
    const int wm = wid >> 2;      // 0..1 -> 64 rows
    const int wn = wid & 3;       // 0..3 -> 32 cols
    const int row0 = blockIdx.y * BM;
    const int col0 = blockIdx.x * BN;

    // ldmatrix selectors (proven mappings)
    const int lr7 = lane & 7;
    const int mi  = lane >> 3;
    const int a_off = (lr7 + 8 * (mi & 1)) * LDH + 8 * (mi >> 1);
    const int b_off = lr7 * LDH + 8 * (mi & 1) + (mi >> 1) * 8 * LDH;

    // staging loader: kg = float4 index along K-panel (0..15), lr = row 0..15 (+16i)
    const int kg = tid & 15;
    const int lr = tid >> 4;
    const float* Ag = A  + (size_t)(row0 + lr) * K + kg * 4;
    const float* Bg = Bw + (size_t)(col0 + lr) * K + kg * 4;

    float c[4][4][4];
#pragma unroll
    for (int mt = 0; mt < 4; mt++)
#pragma unroll
        for (int nt = 0; nt < 4; nt++)
#pragma unroll
            for (int r = 0; r < 4; r++) c[mt][nt][r] = 0.f;

    const __half* Awp = &As[(wm * 64) * LDH];
    const __half* Bwp = &Bs[(wn * 32) * LDH];

    for (int kp = 0; kp < K; kp += BK) {
        // register stage + fp16 convert
        float4 av[8], bv[8];
#pragma unroll
        for (int i = 0; i < 8; i++) {
            av[i] = *(const float4*)(Ag + (size_t)i * 16 * K + kp);
            bv[i] = *(const float4*)(Bg + (size_t)i * 16 * K + kp);
        }
        uint2 ap[8], bp[8];
#pragma unroll
        for (int i = 0; i < 8; i++) {
            ap[i] = make_uint2(packh2(av[i].x, av[i].y), packh2(av[i].z, av[i].w));
            bp[i] = make_uint2(packh2(bv[i].x, bv[i].y), packh2(bv[i].z, bv[i].w));
        }
        __syncthreads();   // previous panel fully consumed
#pragma unroll
        for (int i = 0; i < 8; i++) {
            *(uint2*)&As[(lr + i * 16) * LDH + kg * 4] = ap[i];
            *(uint2*)&Bs[(lr + i * 16) * LDH + kg * 4] = bp[i];
        }
        __syncthreads();

#pragma unroll
        for (int kq = 0; kq < BK; kq += 16) {
            uint32_t af[4][4];
#pragma unroll
            for (int mt = 0; mt < 4; mt++)
                ldsm_x4(af[mt], Awp + mt * 16 * LDH + a_off + kq);
#pragma unroll
            for (int p = 0; p < 2; p++) {
                uint32_t bf[4];
                ldsm_x4(bf, Bwp + p * 16 * LDH + b_off + kq);
#pragma unroll
                for (int mt = 0; mt < 4; mt++) {
                    mma_f16(c[mt][2 * p],     af[mt][0], af[mt][1], af[mt][2], af[mt][3],
                            bf[0], bf[1]);
                    mma_f16(c[mt][2 * p + 1], af[mt][0], af[mt][1], af[mt][2], af[mt][3],
                            bf[2], bf[3]);
                }
            }
        }
    }

    // epilogue: bias + store
#pragma unroll
    for (int mt = 0; mt < 4; mt++) {
        int row = row0 + wm * 64 + mt * 16 + g;
#pragma unroll
        for (int nt = 0; nt < 4; nt++) {
            int col = col0 + wn * 32 + nt * 8 + 2 * t;
            float b0 = bias[col], b1 = bias[col + 1];
            float2 v0 = make_float2(c[mt][nt][0] + b0, c[mt][nt][1] + b1);
            float2 v1 = make_float2(c[mt][nt][2] + b0, c[mt][nt][3] + b1);
            *(float2*)&C[(size_t)row * N + col] = v0;
            *(float2*)&C[(size_t)(row + 8) * N + col] = v1;
        }
    }
}

// ---------------- fp16-split flash attention, ldmatrix fragment loads (R13/R14) ----------------
#define SH 72                       // smem row stride in halves (144 B)
#define OQH 0
#define OQL (128 * SH)
#define OKH (2 * 128 * SH)
#define OKL (OKH + 64 * SH)
#define OVH (OKL + 64 * SH)
#define OVL (OVH + 64 * SH)
#define OPS (OVL + 64 * SH)
#define SMH_TOT (OPS + 128 * SH)    // 46080 halves = 92160 B

__global__ __launch_bounds__(256, 2)
void attn_fp16(const float* __restrict__ qkv, float* __restrict__ attn_out)
{
    extern __shared__ __half smh[];

    const int tid  = threadIdx.x;
    const int lane = tid & 31;
    const int w = tid >> 5;
    const int g = lane >> 2;
    const int t = lane & 3;
    const int b = blockIdx.y >> 4, h = blockIdx.y & 15;
    const int qt = (int)gridDim.x - 1 - (int)blockIdx.x;   // heavy CTAs first
    const int q0 = qt * 128;
    const float* base = qkv + (size_t)b * SEQ * QKV_N + h * (3 * HEAD_DIM);
    const float SC = 0.125f * 1.4426950408889634f;   // 1/sqrt(hd) * log2(e)

    // ---- load Q tile, split into fp16 hi/lo ----
#pragma unroll
    for (int i = 0; i < 8; i++) {
        int idx = tid + i * 256;
        int r = idx >> 4, c4 = (idx & 15) << 2;
        float4 q = *(const float4*)(base + (size_t)(q0 + r) * QKV_N + c4);
        float f[4] = {q.x * SC, q.y * SC, q.z * SC, q.w * SC};
        float hh[4], ll[4];
#pragma unroll
        for (int e = 0; e < 4; e++) {
            hh[e] = __half2float(__float2half_rn(f[e]));
            ll[e] = f[e] - hh[e];
        }
        uint32_t* ph = (uint32_t*)&smh[OQH + r * SH + c4];
        uint32_t* pl = (uint32_t*)&smh[OQL + r * SH + c4];
        ph[0] = packh2(hh[0], hh[1]); ph[1] = packh2(hh[2], hh[3]);
        pl[0] = packh2(ll[0], ll[1]); pl[1] = packh2(ll[2], ll[3]);
    }

    float o[8][4];
#pragma unroll
    for (int nt = 0; nt < 8; nt++)
#pragma unroll
        for (int r = 0; r < 4; r++) o[nt][r] = 0.f;
    float m0 = -1e30f, m1 = -1e30f, l0 = 0.f, l1 = 0.f;

    const int wr = w * 16;
    const int myrow = q0 + wr;
    const int rowg0 = myrow + g, rowg1 = myrow + g + 8;
    const int nkt = qt * 2 + 2;

    const int lr7  = lane & 7;
    const int mi   = lane >> 3;
    const int ksel = (lane >> 3) & 1;
    const int nsel = lane >> 4;
    const int a_base = (wr + lr7 + 8 * (mi & 1)) * SH + 8 * (mi >> 1);
    const int b_row  = lr7 * SH + 8 * (mi & 1);
    const int b_pairstep = 16 * SH;
    const int b_mihalf = (mi >> 1) * 8 * SH;

    for (int j = 0; j < nkt; j++) {
        const int k0 = j * 64;
        float4 kk[4], vv[4];
#pragma unroll
        for (int i = 0; i < 4; i++) {
            int idx = tid + i * 256;
            int r = idx >> 4, c4 = (idx & 15) << 2;
            const float* rp = base + (size_t)(k0 + r) * QKV_N + c4;
            kk[i] = *(const float4*)(rp + HEAD_DIM);
            vv[i] = *(const float4*)(rp + 2 * HEAD_DIM);
        }
        __syncthreads();
#pragma unroll
        for (int i = 0; i < 4; i++) {
            int idx = tid + i * 256;
            int r = idx >> 4, c4 = (idx & 15) << 2;
            float kf[4] = {kk[i].x, kk[i].y, kk[i].z, kk[i].w};
            float vf[4] = {vv[i].x, vv[i].y, vv[i].z, vv[i].w};
            float kh[4], kl[4], vh[4], vl[4];
#pragma unroll
            for (int e = 0; e < 4; e++) {
                kh[e] = __half2float(__float2half_rn(kf[e])); kl[e] = kf[e] - kh[e];
                vh[e] = __half2float(__float2half_rn(vf[e])); vl[e] = vf[e] - vh[e];
            }
            uint32_t* p;
            p = (uint32_t*)&smh[OKH + r * SH + c4];
            p[0] = packh2(kh[0], kh[1]); p[1] = packh2(kh[2], kh[3]);
            p = (uint32_t*)&smh[OKL + r * SH + c4];
            p[0] = packh2(kl[0], kl[1]); p[1] = packh2(kl[2], kl[3]);
            p = (uint32_t*)&smh[OVH + r * SH + c4];
            p[0] = packh2(vh[0], vh[1]); p[1] = packh2(vh[2], vh[3]);
            p = (uint32_t*)&smh[OVL + r * SH + c4];
            p[0] = packh2(vl[0], vl[1]); p[1] = packh2(vl[2], vl[3]);
        }
        __syncthreads();

        if (k0 <= myrow + 15) {
            float s[8][4];
#pragma unroll
            for (int nt = 0; nt < 8; nt++)
#pragma unroll
                for (int r = 0; r < 4; r++) s[nt][r] = 0.f;

#pragma unroll
            for (int kq = 0; kq < 4; kq++) {
                const int kc = kq * 16;
                uint32_t ah[4], al[4];
                ldsm_x4(ah, &smh[OQH + a_base + kc]);
                ldsm_x4(al, &smh[OQL + a_base + kc]);
#pragma unroll
                for (int p = 0; p < 4; p++) {
                    uint32_t bh[4], bl[4];
                    ldsm_x4(bh, &smh[OKH + b_row + p * b_pairstep + b_mihalf + kc]);
                    ldsm_x4(bl, &smh[OKL + b_row + p * b_pairstep + b_mihalf + kc]);
                    mma_f16(s[2 * p],     ah[0], ah[1], ah[2], ah[3], bh[0], bh[1]);
                    mma_f16(s[2 * p],     al[0], al[1], al[2], al[3], bh[0], bh[1]);
                    mma_f16(s[2 * p],     ah[0], ah[1], ah[2], ah[3], bl[0], bl[1]);
                    mma_f16(s[2 * p + 1], ah[0], ah[1], ah[2], ah[3], bh[2], bh[3]);
                    mma_f16(s[2 * p + 1], al[0], al[1], al[2], al[3], bh[2], bh[3]);
                    mma_f16(s[2 * p + 1], ah[0], ah[1], ah[2], ah[3], bl[2], bl[3]);
                }
            }

            if (k0 + 63 > myrow) {
#pragma unroll
                for (int nt = 0; nt < 8; nt++) {
                    int c = k0 + nt * 8 + 2 * t;
                    if (c > rowg0)     s[nt][0] = -1e30f;
                    if (c + 1 > rowg0) s[nt][1] = -1e30f;
                    if (c > rowg1)     s[nt][2] = -1e30f;
                    if (c + 1 > rowg1) s[nt][3] = -1e30f;
                }
            }

            float rm0 = -1e30f, rm1 = -1e30f;
#pragma unroll
            for (int nt = 0; nt < 8; nt++) {
                rm0 = fmaxf(rm0, fmaxf(s[nt][0], s[nt][1]));
                rm1 = fmaxf(rm1, fmaxf(s[nt][2], s[nt][3]));
            }
            rm0 = fmaxf(rm0, __shfl_xor_sync(0xffffffffu, rm0, 1));
            rm0 = fmaxf(rm0, __shfl_xor_sync(0xffffffffu, rm0, 2));
            rm1 = fmaxf(rm1, __shfl_xor_sync(0xffffffffu, rm1, 1));
            rm1 = fmaxf(rm1, __shfl_xor_sync(0xffffffffu, rm1, 2));
            float mn0 = fmaxf(m0, rm0), mn1 = fmaxf(m1, rm1);
            float alp0 = exp2f(m0 - mn0), alp1 = exp2f(m1 - mn1);
            float rs0 = 0.f, rs1 = 0.f;
#pragma unroll
            for (int nt = 0; nt < 8; nt++) {
                s[nt][0] = exp2f(s[nt][0] - mn0);
                s[nt][1] = exp2f(s[nt][1] - mn0);
                s[nt][2] = exp2f(s[nt][2] - mn1);
                s[nt][3] = exp2f(s[nt][3] - mn1);
                rs0 += s[nt][0] + s[nt][1];
                rs1 += s[nt][2] + s[nt][3];
                *(uint32_t*)&smh[OPS + (wr + g) * SH + nt * 8 + 2 * t] =
                    packh2(s[nt][0], s[nt][1]);
                *(uint32_t*)&smh[OPS + (wr + g + 8) * SH + nt * 8 + 2 * t] =
                    packh2(s[nt][2], s[nt][3]);
            }
            rs0 += __shfl_xor_sync(0xffffffffu, rs0, 1);
            rs0 += __shfl_xor_sync(0xffffffffu, rs0, 2);
            rs1 += __shfl_xor_sync(0xffffffffu, rs1, 1);
            rs1 += __shfl_xor_sync(0xffffffffu, rs1, 2);
            l0 = l0 * alp0 + rs0;  l1 = l1 * alp1 + rs1;
            m0 = mn0;  m1 = mn1;
#pragma unroll
            for (int nt = 0; nt < 8; nt++) {
                o[nt][0] *= alp0; o[nt][1] *= alp0;
                o[nt][2] *= alp1; o[nt][3] *= alp1;
            }
            __syncwarp();

#pragma unroll
            for (int kq = 0; kq < 4; kq++) {
                const int kc = kq * 16;
                uint32_t pa[4];
                ldsm_x4(pa, &smh[OPS + a_base + kc]);
                const int vrow = (kc + lr7 + 8 * ksel) * SH + nsel * 8;
#pragma unroll
                for (int np = 0; np < 4; np++) {
                    uint32_t bh[4], bl[4];
                    ldsm_x4_t(bh, &smh[OVH + vrow + np * 16]);
                    ldsm_x4_t(bl, &smh[OVL + vrow + np * 16]);
                    mma_f16(o[np * 2],     pa[0], pa[1], pa[2], pa[3], bh[0], bh[1]);
                    mma_f16(o[np * 2],     pa[0], pa[1], pa[2], pa[3], bl[0], bl[1]);
                    mma_f16(o[np * 2 + 1], pa[0], pa[1], pa[2], pa[3], bh[2], bh[3]);
                    mma_f16(o[np * 2 + 1], pa[0], pa[1], pa[2], pa[3], bl[2], bl[3]);
                }
            }
            __syncwarp();
        }
    }

    // ---- normalize + write [B,H,S,hd] ----
    float inv0 = 1.0f / l0, inv1 = 1.0f / l1;
    float* op = attn_out + ((size_t)b * NUM_HEADS + h) * SEQ * HEAD_DIM;
#pragma unroll
    for (int nt = 0; nt < 8; nt++) {
        int c = nt * 8 + 2 * t;
        *(float2*)&op[(size_t)rowg0 * HEAD_DIM + c] =
            make_float2(o[nt][0] * inv0, o[nt][1] * inv0);
        *(float2*)&op[(size_t)rowg1 * HEAD_DIM + c] =
            make_float2(o[nt][2] * inv1, o[nt][3] * inv1);
    }
}

// ---------------- launch ----------------
extern "C" void kernel_launch(void* const* d_in, const int* in_sizes, int n_in,
                              void* d_out, int out_size)
{
    const float* x    = (const float*)d_in[0];
    const float* Wqkv = (const float*)d_in[1];
    const float* bqkv = (const float*)d_in[2];
    const float* Wo   = (const float*)d_in[3];
    const float* bo   = (const float*)d_in[4];
    float* out = (float*)d_out;

    float* qkv_ptr = nullptr;
    float* attn_ptr = nullptr;
    cudaGetSymbolAddress((void**)&qkv_ptr, g_qkv);
    cudaGetSymbolAddress((void**)&attn_ptr, g_attn);

    const int attn_smem = SMH_TOT * (int)sizeof(__half);   // 92160 B
    cudaFuncSetAttribute(attn_fp16, cudaFuncAttributeMaxDynamicSharedMemorySize, attn_smem);

    // 1) qkv = x @ Wqkv^T + bqkv   (fp16 m16n8k16 tensor cores, BK=64)
    gemm_f16<<<dim3(QKV_N / BN, M_TOT / BM), 256>>>(x, Wqkv, bqkv, qkv_ptr, QKV_N, D_MODEL);
    // 2) causal flash attention (fp16-split, ldmatrix fragment loads)
    attn_fp16<<<dim3(SEQ / 128, BATCH * NUM_HEADS), 256, attn_smem>>>(qkv_ptr, attn_ptr);
    // 3) out = attn @ Wo^T + bo    (fp16 m16n8k16 tensor cores, BK=64)
    gemm_f16<<<dim3(D_MODEL / BN, M_TOT / BM), 256>>>(attn_ptr, Wo, bo, out, D_MODEL, D_MODEL);
}